// round 8
// baseline (speedup 1.0000x reference)
#include <cuda_runtime.h>
#include <cuda_bf16.h>

// ZBL repulsion energy, R8: R1 structure (full-occupancy LDG gathers) with
// explicit MLP phase-batching and a conflict-free replicated z-LUT.
//
// Lessons: R6 (DSMEM) and R7 (smem table head) both lost — table (500KB) >
// SM-local storage (228KB), so gather L2 traffic is structurally fixed and
// occupancy/L1 capacity must not be sacrificed. R1 sits at L2=83%/L1=81%
// with issue=12%; this round pushes utilization via ILP:
//  - PPT=8, phases: [16 idx loads] -> [16 gathers] -> [r/cv loads] -> [math+RED]
//  - z-LUT replicated x32 lanes in smem -> bank == lane -> zero conflicts.

#define KEHALF 7.199822675975274f
#define LOG2E  1.4426950408889634f
#define MAX_ATOMS 524288          // problem uses 500,000
#define TPB 256
#define PPT 8

__device__ unsigned char g_Z8[MAX_ATOMS];
__device__ float g_zlut[128];     // z = Z^sp(apow), indexed by Z
__device__ float g_c[12];         // b1..b4 (=sp(a_k)*sp(adiv)*log2e), c1n..c4n

__device__ __forceinline__ float ex2f(float x) {
    float y; asm("ex2.approx.ftz.f32 %0, %1;" : "=f"(y) : "f"(x)); return y;
}
__device__ __forceinline__ float frcpf(float x) {
    float y; asm("rcp.approx.ftz.f32 %0, %1;" : "=f"(y) : "f"(x)); return y;
}
__device__ __forceinline__ unsigned ldZ(unsigned idx) {
    unsigned v;
    asm("ld.global.nc.L1::evict_last.u8 %0, [%1];" : "=r"(v) : "l"(g_Z8 + idx));
    return v;
}

__global__ void prep_kernel(const float* __restrict__ Zf, int natoms,
                            float* __restrict__ out, int out_n,
                            const float* adiv, const float* apow,
                            const float* c1, const float* c2,
                            const float* c3, const float* c4,
                            const float* a1, const float* a2,
                            const float* a3, const float* a4) {
    int t = blockIdx.x * blockDim.x + threadIdx.x;
    if (t < MAX_ATOMS)
        g_Z8[t] = (t < natoms) ? (unsigned char)__float2int_rn(Zf[t]) : 0;
    if (t < out_n)
        out[t] = 0.0f;

    if (blockIdx.x == 0) {
        if (threadIdx.x < 128) {
            float spapow = log1pf(expf(*apow));
            g_zlut[threadIdx.x] = (threadIdx.x == 0) ? 0.0f
                                : powf((float)threadIdx.x, spapow);
        }
        if (threadIdx.x == 0) {
            float spadiv = log1pf(expf(*adiv));
            float sa1 = log1pf(expf(*a1)), sa2 = log1pf(expf(*a2));
            float sa3 = log1pf(expf(*a3)), sa4 = log1pf(expf(*a4));
            float c1p = log1pf(expf(*c1)), c2p = log1pf(expf(*c2));
            float c3p = log1pf(expf(*c3)), c4p = log1pf(expf(*c4));
            float inv = 1.0f / (c1p + c2p + c3p + c4p);
            g_c[0] = sa1 * spadiv * LOG2E;  g_c[1] = sa2 * spadiv * LOG2E;
            g_c[2] = sa3 * spadiv * LOG2E;  g_c[3] = sa4 * spadiv * LOG2E;
            g_c[4] = c1p * inv; g_c[5] = c2p * inv;
            g_c[6] = c3p * inv; g_c[7] = c4p * inv;
        }
    }
}

struct PairConsts { float b1, b2, b3, b4, c1n, c2n, c3n, c4n; };

__device__ __forceinline__ void finish_pair(float r, float cv,
                                            unsigned zi, unsigned zj, int i,
                                            const float* __restrict__ s_zr,
                                            int lane,
                                            const PairConsts& K,
                                            float* __restrict__ out) {
    // replicated LUT: address bank == lane -> conflict-free
    float s  = s_zr[(zi << 5) + lane] + s_zr[(zj << 5) + lane];
    float t  = s * r;
    float f  = K.c1n * ex2f(-K.b1 * t)
             + K.c2n * ex2f(-K.b2 * t)
             + K.c3n * ex2f(-K.b3 * t)
             + K.c4n * ex2f(-K.b4 * t);
    float zz = (float)(zi * zj);
    atomicAdd(out + i, (KEHALF * cv * zz) * f * frcpf(r));
}

extern "C" __global__ void __launch_bounds__(TPB)
pair_kernel(const float* __restrict__ rij, const float* __restrict__ cv,
            const int* __restrict__ ii, const int* __restrict__ jj,
            float* __restrict__ out, int P) {
    __shared__ float s_zr[128 * 32];   // z-LUT replicated per lane (16KB)
    __shared__ float s_c8[8];
    int tid = threadIdx.x;
    int lane = tid & 31;

    for (int k = tid; k < 128 * 32; k += TPB)
        s_zr[k] = g_zlut[k >> 5];
    if (tid < 8) s_c8[tid] = g_c[tid];
    __syncthreads();

    PairConsts K;
    K.b1  = s_c8[0]; K.b2  = s_c8[1]; K.b3  = s_c8[2]; K.b4  = s_c8[3];
    K.c1n = s_c8[4]; K.c2n = s_c8[5]; K.c3n = s_c8[6]; K.c4n = s_c8[7];

    long base = ((long)blockIdx.x * TPB + tid) * PPT;

    if (base + PPT <= (long)P) {
        // Phase 1: index loads (coalesced 16B)
        int4 iA = __ldcs((const int4*)(ii + base));
        int4 iB = __ldcs((const int4*)(ii + base + 4));
        int4 jA = __ldcs((const int4*)(jj + base));
        int4 jB = __ldcs((const int4*)(jj + base + 4));
        // Phase 2: all 16 gathers back-to-back (max MLP)
        unsigned zi0 = ldZ((unsigned)iA.x), zi1 = ldZ((unsigned)iA.y);
        unsigned zi2 = ldZ((unsigned)iA.z), zi3 = ldZ((unsigned)iA.w);
        unsigned zi4 = ldZ((unsigned)iB.x), zi5 = ldZ((unsigned)iB.y);
        unsigned zi6 = ldZ((unsigned)iB.z), zi7 = ldZ((unsigned)iB.w);
        unsigned zj0 = ldZ((unsigned)jA.x), zj1 = ldZ((unsigned)jA.y);
        unsigned zj2 = ldZ((unsigned)jA.z), zj3 = ldZ((unsigned)jA.w);
        unsigned zj4 = ldZ((unsigned)jB.x), zj5 = ldZ((unsigned)jB.y);
        unsigned zj6 = ldZ((unsigned)jB.z), zj7 = ldZ((unsigned)jB.w);
        // Phase 3: streaming r/cv loads land inside gather latency
        float4 rA = __ldcs((const float4*)(rij + base));
        float4 rB = __ldcs((const float4*)(rij + base + 4));
        float4 cA = __ldcs((const float4*)(cv + base));
        float4 cB = __ldcs((const float4*)(cv + base + 4));
        // Phase 4: math + scatter
        finish_pair(rA.x, cA.x, zi0, zj0, iA.x, s_zr, lane, K, out);
        finish_pair(rA.y, cA.y, zi1, zj1, iA.y, s_zr, lane, K, out);
        finish_pair(rA.z, cA.z, zi2, zj2, iA.z, s_zr, lane, K, out);
        finish_pair(rA.w, cA.w, zi3, zj3, iA.w, s_zr, lane, K, out);
        finish_pair(rB.x, cB.x, zi4, zj4, iB.x, s_zr, lane, K, out);
        finish_pair(rB.y, cB.y, zi5, zj5, iB.y, s_zr, lane, K, out);
        finish_pair(rB.z, cB.z, zi6, zj6, iB.z, s_zr, lane, K, out);
        finish_pair(rB.w, cB.w, zi7, zj7, iB.w, s_zr, lane, K, out);
    } else {
        for (long p = base; p < (long)P; ++p) {
            int i = ii[p], j = jj[p];
            unsigned zi = ldZ((unsigned)i);
            unsigned zj = ldZ((unsigned)j);
            finish_pair(rij[p], cv[p], zi, zj, i, s_zr, lane, K, out);
        }
    }
}

extern "C" void kernel_launch(void* const* d_in, const int* in_sizes, int n_in,
                              void* d_out, int out_size) {
    const float* Zf   = (const float*)d_in[n_in - 15];
    const float* rij  = (const float*)d_in[n_in - 14];
    const float* cutv = (const float*)d_in[n_in - 13];
    const int*   ii   = (const int*)  d_in[n_in - 12];
    const int*   jj   = (const int*)  d_in[n_in - 11];
    const float* adiv = (const float*)d_in[n_in - 10];
    const float* apow = (const float*)d_in[n_in - 9];
    const float* c1   = (const float*)d_in[n_in - 8];
    const float* c2   = (const float*)d_in[n_in - 7];
    const float* c3   = (const float*)d_in[n_in - 6];
    const float* c4   = (const float*)d_in[n_in - 5];
    const float* a1   = (const float*)d_in[n_in - 4];
    const float* a2   = (const float*)d_in[n_in - 3];
    const float* a3   = (const float*)d_in[n_in - 2];
    const float* a4   = (const float*)d_in[n_in - 1];

    int natoms = in_sizes[n_in - 15];
    int P      = in_sizes[n_in - 14];
    float* out = (float*)d_out;

    int pb = (MAX_ATOMS + 255) / 256;
    prep_kernel<<<pb, 256>>>(Zf, natoms, out, out_size,
                             adiv, apow, c1, c2, c3, c4, a1, a2, a3, a4);

    long nthreads = ((long)P + PPT - 1) / PPT;
    int blocks = (int)((nthreads + TPB - 1) / TPB);
    pair_kernel<<<blocks, TPB>>>(rij, cutv, ii, jj, out, P);
}

// round 9
// speedup vs baseline: 1.0470x; 1.0470x over previous
#include <cuda_runtime.h>
#include <cuda_bf16.h>

// ZBL repulsion energy, R9: exact R1 structure (best: 176.9us, occ 90%,
// L1=81%/L2=83% co-saturated at the scattered-wavefront floor) with ONE change:
// the 128-entry z-LUT is replicated x32 lanes in smem so both per-pair LDS
// lookups are bank-conflict-free (bank == lane). LDS conflict phases share the
// saturated L1tex/shared pipe, so removing ~6 phases/pair trims the floor.
// Also: output zeroing folded into prep (removes the memset graph node).
//
// History: R6 DSMEM cluster 444us (fabric-bound), R7 smem table head 207us
// (L1 displacement + occ loss), R8 PPT=8 batching 209us (occ 90->70). The
// binder is L1tex wavefront throughput; occupancy and L1 capacity are sacred.

#define KEHALF 7.199822675975274f
#define LOG2E  1.4426950408889634f
#define MAX_ATOMS 524288          // problem uses 500,000
#define TPB 256
#define PPT 4

__device__ unsigned char g_Z8[MAX_ATOMS];
__device__ float g_zlut[128];     // z = Z^sp(apow), indexed by Z
__device__ float g_c[12];         // b1..b4 (=sp(a_k)*sp(adiv)*log2e), c1n..c4n

__device__ __forceinline__ float ex2f(float x) {
    float y; asm("ex2.approx.ftz.f32 %0, %1;" : "=f"(y) : "f"(x)); return y;
}
__device__ __forceinline__ float frcpf(float x) {
    float y; asm("rcp.approx.ftz.f32 %0, %1;" : "=f"(y) : "f"(x)); return y;
}

__global__ void prep_kernel(const float* __restrict__ Zf, int natoms,
                            float* __restrict__ out, int out_n,
                            const float* adiv, const float* apow,
                            const float* c1, const float* c2,
                            const float* c3, const float* c4,
                            const float* a1, const float* a2,
                            const float* a3, const float* a4) {
    int t = blockIdx.x * blockDim.x + threadIdx.x;
    if (t < MAX_ATOMS)
        g_Z8[t] = (t < natoms) ? (unsigned char)__float2int_rn(Zf[t]) : 0;
    if (t < out_n)
        out[t] = 0.0f;                       // replaces cudaMemsetAsync node

    if (blockIdx.x == 0) {
        if (threadIdx.x < 128) {
            float spapow = log1pf(expf(*apow));
            g_zlut[threadIdx.x] = (threadIdx.x == 0) ? 0.0f
                                : powf((float)threadIdx.x, spapow);
        }
        if (threadIdx.x == 0) {
            float spadiv = log1pf(expf(*adiv));
            float sa1 = log1pf(expf(*a1)), sa2 = log1pf(expf(*a2));
            float sa3 = log1pf(expf(*a3)), sa4 = log1pf(expf(*a4));
            float c1p = log1pf(expf(*c1)), c2p = log1pf(expf(*c2));
            float c3p = log1pf(expf(*c3)), c4p = log1pf(expf(*c4));
            float inv = 1.0f / (c1p + c2p + c3p + c4p);
            g_c[0] = sa1 * spadiv * LOG2E;  g_c[1] = sa2 * spadiv * LOG2E;
            g_c[2] = sa3 * spadiv * LOG2E;  g_c[3] = sa4 * spadiv * LOG2E;
            g_c[4] = c1p * inv; g_c[5] = c2p * inv;
            g_c[6] = c3p * inv; g_c[7] = c4p * inv;
        }
    }
}

struct PairConsts { float b1, b2, b3, b4, c1n, c2n, c3n, c4n; };

__device__ __forceinline__ void do_pair(float r, float cv, int i, int j,
                                        const float* __restrict__ s_zr,
                                        int lane,
                                        const PairConsts& K,
                                        float* __restrict__ out) {
    unsigned zi = g_Z8[i];
    unsigned zj = g_Z8[j];
    // Replicated LUT: address bank == lane -> conflict-free LDS.
    float s  = s_zr[(zi << 5) + lane] + s_zr[(zj << 5) + lane];
    float t  = s * r;
    float f  = K.c1n * ex2f(-K.b1 * t)
             + K.c2n * ex2f(-K.b2 * t)
             + K.c3n * ex2f(-K.b3 * t)
             + K.c4n * ex2f(-K.b4 * t);
    float zz = (float)(zi * zj);           // exact integer product
    float contrib = (KEHALF * cv * zz) * f * frcpf(r);
    atomicAdd(out + i, contrib);           // return unused -> RED.ADD.F32
}

extern "C" __global__ void __launch_bounds__(TPB)
pair_kernel(const float* __restrict__ rij, const float* __restrict__ cv,
            const int* __restrict__ ii, const int* __restrict__ jj,
            float* __restrict__ out, int P) {
    __shared__ float s_zr[128 * 32];   // z-LUT replicated per lane (16KB)
    __shared__ float s_c8[8];
    int tid = threadIdx.x;
    int lane = tid & 31;

    // Broadcast fill: each lane writes its own bank slots (conflict-free).
    #pragma unroll 4
    for (int k = tid; k < 128 * 32; k += TPB)
        s_zr[k] = g_zlut[k >> 5];
    if (tid < 8) s_c8[tid] = g_c[tid];
    __syncthreads();

    PairConsts K;
    K.b1  = s_c8[0]; K.b2  = s_c8[1]; K.b3  = s_c8[2]; K.b4  = s_c8[3];
    K.c1n = s_c8[4]; K.c2n = s_c8[5]; K.c3n = s_c8[6]; K.c4n = s_c8[7];

    long base = (long)(blockIdx.x * TPB + tid) * PPT;
    if (base + PPT <= (long)P) {
        float4 r4 = *(const float4*)(rij + base);
        float4 c4 = *(const float4*)(cv + base);
        int4   i4 = *(const int4*)(ii + base);
        int4   j4 = *(const int4*)(jj + base);
        do_pair(r4.x, c4.x, i4.x, j4.x, s_zr, lane, K, out);
        do_pair(r4.y, c4.y, i4.y, j4.y, s_zr, lane, K, out);
        do_pair(r4.z, c4.z, i4.z, j4.z, s_zr, lane, K, out);
        do_pair(r4.w, c4.w, i4.w, j4.w, s_zr, lane, K, out);
    } else {
        for (long p = base; p < (long)P; ++p)
            do_pair(rij[p], cv[p], ii[p], jj[p], s_zr, lane, K, out);
    }
}

extern "C" void kernel_launch(void* const* d_in, const int* in_sizes, int n_in,
                              void* d_out, int out_size) {
    const float* Zf   = (const float*)d_in[n_in - 15];
    const float* rij  = (const float*)d_in[n_in - 14];
    const float* cutv = (const float*)d_in[n_in - 13];
    const int*   ii   = (const int*)  d_in[n_in - 12];
    const int*   jj   = (const int*)  d_in[n_in - 11];
    const float* adiv = (const float*)d_in[n_in - 10];
    const float* apow = (const float*)d_in[n_in - 9];
    const float* c1   = (const float*)d_in[n_in - 8];
    const float* c2   = (const float*)d_in[n_in - 7];
    const float* c3   = (const float*)d_in[n_in - 6];
    const float* c4   = (const float*)d_in[n_in - 5];
    const float* a1   = (const float*)d_in[n_in - 4];
    const float* a2   = (const float*)d_in[n_in - 3];
    const float* a3   = (const float*)d_in[n_in - 2];
    const float* a4   = (const float*)d_in[n_in - 1];

    int natoms = in_sizes[n_in - 15];
    int P      = in_sizes[n_in - 14];
    float* out = (float*)d_out;

    int pb = (MAX_ATOMS + 255) / 256;
    prep_kernel<<<pb, 256>>>(Zf, natoms, out, out_size,
                             adiv, apow, c1, c2, c3, c4, a1, a2, a3, a4);

    long nthreads = ((long)P + PPT - 1) / PPT;
    int blocks = (int)((nthreads + TPB - 1) / TPB);
    pair_kernel<<<blocks, TPB>>>(rij, cutv, ii, jj, out, P);
}